// round 5
// baseline (speedup 1.0000x reference)
#include <cuda_runtime.h>
#include <float.h>

#define NTOK 4096
#define DEMB 1024
#define NH   8
#define DH   128
#define CWW  256
#define QK_SCALE 0.08838834764831845f  // 1/sqrt(128)

typedef unsigned long long u64;

// ---------------- f32x2 packed-math helpers ---------------------------------
__device__ __forceinline__ u64 pack2(float x, float y) {
    u64 r; asm("mov.b64 %0, {%1, %2};" : "=l"(r) : "f"(x), "f"(y)); return r;
}
__device__ __forceinline__ float2 unpack2(u64 v) {
    float2 r; asm("mov.b64 {%0, %1}, %2;" : "=f"(r.x), "=f"(r.y) : "l"(v)); return r;
}
__device__ __forceinline__ void ffma2(u64& d, u64 a, u64 b) {
    asm("fma.rn.f32x2 %0, %1, %2, %0;" : "+l"(d) : "l"(a), "l"(b));
}
__device__ __forceinline__ void fmul2(u64& d, u64 a) {
    asm("mul.rn.f32x2 %0, %0, %1;" : "+l"(d) : "l"(a));
}

// ---------------- scratch (static device memory; no allocations) ------------
__device__ float4 g_q4[NTOK * DH / 4];
__device__ float4 g_k4[NTOK * DH / 4];
__device__ float4 g_v4[NTOK * DH / 4];
__device__ float4 g_av4[NTOK * DH / 4];
__device__ float4 g_delta4[NTOK * DEMB / 4];

// ---------------- SGEMM: C[n][m] = sum_k A[n][k] * B[m][k] ------------------
// Block tile ROWS(n) x 128(m), K-tile 16, 256 threads, double-buffered smem,
// f32x2 packed accumulation (col pairs natural from smem, A scalar broadcast).
template <int K, int M, int ROWS>
__device__ __forceinline__ void gemm_body(const float* __restrict__ A,
                                          const float* __restrict__ B,
                                          float* __restrict__ C) {
    constexpr int RPT = ROWS / 16;     // rows per thread (4 or 8)
    constexpr int RW  = ROWS + 4;      // padded row width
    constexpr int AV  = ROWS / 64;     // A float4 stage loads per thread (1 or 2)
    constexpr int KT  = K / 16;

    __shared__ alignas(16) float As[2][16][RW];
    __shared__ alignas(16) float Bs[2][16][132];

    const int tid = threadIdx.x;
    const int tx = tid & 15;           // 8 output cols each (4 f32x2 pairs)
    const int ty = tid >> 4;           // RPT output rows each
    const int n0 = blockIdx.y * ROWS;
    const int m0 = blockIdx.x * 128;
    const float* Ag = A + (size_t)n0 * K;
    const float* Bg = B + (size_t)m0 * K;

    u64 acc[RPT][4];
#pragma unroll
    for (int i = 0; i < RPT; i++)
#pragma unroll
        for (int j = 0; j < 4; j++) acc[i][j] = 0ULL;

    float4 areg[AV], breg[2];

    // ---- stage tile 0 ----
#pragma unroll
    for (int v = 0; v < AV; v++) {
        int idx = tid + 256 * v;
        areg[v] = *(const float4*)(Ag + (size_t)(idx >> 2) * K + ((idx & 3) << 2));
    }
#pragma unroll
    for (int v = 0; v < 2; v++) {
        int idx = tid + 256 * v;
        breg[v] = *(const float4*)(Bg + (size_t)(idx >> 2) * K + ((idx & 3) << 2));
    }
#pragma unroll
    for (int v = 0; v < AV; v++) {
        int idx = tid + 256 * v;
        int row = idx >> 2, kq = (idx & 3) << 2;
        As[0][kq + 0][row] = areg[v].x;
        As[0][kq + 1][row] = areg[v].y;
        As[0][kq + 2][row] = areg[v].z;
        As[0][kq + 3][row] = areg[v].w;
    }
#pragma unroll
    for (int v = 0; v < 2; v++) {
        int idx = tid + 256 * v;
        int row = idx >> 2, kq = (idx & 3) << 2;
        Bs[0][kq + 0][row] = breg[v].x;
        Bs[0][kq + 1][row] = breg[v].y;
        Bs[0][kq + 2][row] = breg[v].z;
        Bs[0][kq + 3][row] = breg[v].w;
    }
    __syncthreads();

    for (int kt = 0; kt < KT; kt++) {
        const int cur = kt & 1;
        // prefetch next tile into registers (overlapped with compute)
        if (kt + 1 < KT) {
            const int k0 = (kt + 1) * 16;
#pragma unroll
            for (int v = 0; v < AV; v++) {
                int idx = tid + 256 * v;
                areg[v] = *(const float4*)(Ag + (size_t)(idx >> 2) * K + k0 + ((idx & 3) << 2));
            }
#pragma unroll
            for (int v = 0; v < 2; v++) {
                int idx = tid + 256 * v;
                breg[v] = *(const float4*)(Bg + (size_t)(idx >> 2) * K + k0 + ((idx & 3) << 2));
            }
        }
        // compute from current buffer
#pragma unroll
        for (int kk = 0; kk < 16; kk++) {
            const ulonglong2 b01 = *(const ulonglong2*)&Bs[cur][kk][tx * 8];
            const ulonglong2 b23 = *(const ulonglong2*)&Bs[cur][kk][tx * 8 + 4];
            u64 bb0 = b01.x, bb1 = b01.y, bb2 = b23.x, bb3 = b23.y;
#pragma unroll
            for (int v = 0; v < RPT / 4; v++) {
                float4 av = *(const float4*)&As[cur][kk][ty * RPT + v * 4];
                float aa[4] = {av.x, av.y, av.z, av.w};
#pragma unroll
                for (int q = 0; q < 4; q++) {
                    u64 ap = pack2(aa[q], aa[q]);
                    const int i = v * 4 + q;
                    ffma2(acc[i][0], ap, bb0);
                    ffma2(acc[i][1], ap, bb1);
                    ffma2(acc[i][2], ap, bb2);
                    ffma2(acc[i][3], ap, bb3);
                }
            }
        }
        // publish next tile
        if (kt + 1 < KT) {
            const int nxt = cur ^ 1;
#pragma unroll
            for (int v = 0; v < AV; v++) {
                int idx = tid + 256 * v;
                int row = idx >> 2, kq = (idx & 3) << 2;
                As[nxt][kq + 0][row] = areg[v].x;
                As[nxt][kq + 1][row] = areg[v].y;
                As[nxt][kq + 2][row] = areg[v].z;
                As[nxt][kq + 3][row] = areg[v].w;
            }
#pragma unroll
            for (int v = 0; v < 2; v++) {
                int idx = tid + 256 * v;
                int row = idx >> 2, kq = (idx & 3) << 2;
                Bs[nxt][kq + 0][row] = breg[v].x;
                Bs[nxt][kq + 1][row] = breg[v].y;
                Bs[nxt][kq + 2][row] = breg[v].z;
                Bs[nxt][kq + 3][row] = breg[v].w;
            }
            __syncthreads();
        }
    }

#pragma unroll
    for (int i = 0; i < RPT; i++) {
        float2 c0 = unpack2(acc[i][0]);
        float2 c1 = unpack2(acc[i][1]);
        float2 c2 = unpack2(acc[i][2]);
        float2 c3 = unpack2(acc[i][3]);
        float* cp = C + (size_t)(n0 + ty * RPT + i) * M + m0 + tx * 8;
        *(float4*)cp       = make_float4(c0.x, c0.y, c1.x, c1.y);
        *(float4*)(cp + 4) = make_float4(c2.x, c2.y, c3.x, c3.y);
    }
}

// QKV projections, batched over blockIdx.z (0:q 1:k 2:vd). K=1024, M=128.
// grid (1, 64, 3): 64-row tiles -> 192 blocks (full chip).
__global__ void __launch_bounds__(256) k_gemm_qkv(const float* __restrict__ e,
                                                  const float* __restrict__ Wq,
                                                  const float* __restrict__ Wk,
                                                  const float* __restrict__ Wvd) {
    const float* B = (blockIdx.z == 0) ? Wq : (blockIdx.z == 1 ? Wk : Wvd);
    float* C = (blockIdx.z == 0) ? (float*)g_q4
                                 : (blockIdx.z == 1 ? (float*)g_k4 : (float*)g_v4);
    gemm_body<1024, 128, 64>(e, B, C);
}

// out projection: delta = av @ Wvu[h]^T. K=128, M=1024. grid (8, 32).
__global__ void __launch_bounds__(256) k_gemm_out(const float* __restrict__ Wvu) {
    gemm_body<128, 1024, 128>((const float*)g_av4, Wvu, (float*)g_delta4);
}

// ---------------- banded attention (online softmax, f32x2) ------------------
__global__ void __launch_bounds__(256) k_attn() {
    __shared__ float4 Qs[32 * 32];  // [q][d4]
    __shared__ float4 Kt[32 * 32];  // [d4][key ^ d4]
    __shared__ float4 Vs[32 * 32];  // [key][d4]
    const int tid  = threadIdx.x;
    const int lane = tid & 31;
    const int w    = tid >> 5;
    const int q0   = blockIdx.x * 32;

#pragma unroll
    for (int i = 0; i < 4; i++)
        Qs[tid + 256 * i] = g_q4[q0 * 32 + tid + 256 * i];

    float m[4], l[4];
    u64 o2[4][2];
#pragma unroll
    for (int qi = 0; qi < 4; qi++) {
        m[qi] = -FLT_MAX;
        l[qi] = 0.f;
        o2[qi][0] = 0ULL;
        o2[qi][1] = 0ULL;
    }
    const int jbase = q0 + 4 * w;
    const int lo = (q0 >= CWW) ? (q0 - CWW) : 0;
    const int hi = min(q0 + 31 + CWW, NTOK);  // exclusive key bound

    for (int kc = lo; kc < hi; kc += 32) {
        __syncthreads();
#pragma unroll
        for (int i = 0; i < 4; i++) {
            int idx = tid + 256 * i;   // 0..1023
            int key = idx >> 5;        // 0..31
            int d4  = idx & 31;        // == lane
            int kg  = kc + key;
            float4 kv = make_float4(0.f, 0.f, 0.f, 0.f);
            float4 vv = make_float4(0.f, 0.f, 0.f, 0.f);
            if (kg < NTOK) {
                kv = g_k4[kg * 32 + d4];
                vv = g_v4[kg * 32 + d4];
            }
            Kt[(d4 << 5) + (key ^ d4)] = kv;
            Vs[(key << 5) + d4] = vv;
        }
        __syncthreads();

        // scores for key = kc + lane (f32x2 dot accumulation)
        u64 s2[4][2];
#pragma unroll
        for (int qi = 0; qi < 4; qi++) { s2[qi][0] = 0ULL; s2[qi][1] = 0ULL; }
#pragma unroll 8
        for (int d4 = 0; d4 < 32; d4++) {
            ulonglong2 kv = *(const ulonglong2*)&Kt[(d4 << 5) + (lane ^ d4)];
#pragma unroll
            for (int qi = 0; qi < 4; qi++) {
                ulonglong2 qv = *(const ulonglong2*)&Qs[(4 * w + qi) * 32 + d4];
                ffma2(s2[qi][0], qv.x, kv.x);
                ffma2(s2[qi][1], qv.y, kv.y);
            }
        }

        const int kg = kc + lane;
        float p[4];
#pragma unroll
        for (int qi = 0; qi < 4; qi++) {
            int j = jbase + qi;
            float2 u0 = unpack2(s2[qi][0]);
            float2 u1 = unpack2(s2[qi][1]);
            float sv = ((u0.x + u0.y) + (u1.x + u1.y)) * QK_SCALE;
            bool ok = (kg >= j - CWW) && (kg < j + CWW) && (kg < NTOK);
            sv = ok ? sv : -FLT_MAX;
            float c = sv;
#pragma unroll
            for (int off = 16; off; off >>= 1)
                c = fmaxf(c, __shfl_xor_sync(0xffffffffu, c, off));
            float mn   = fmaxf(m[qi], c);
            float corr = __expf(m[qi] - mn);
            float pv   = __expf(sv - mn);
            float su = pv;
#pragma unroll
            for (int off = 16; off; off >>= 1)
                su += __shfl_xor_sync(0xffffffffu, su, off);
            l[qi] = l[qi] * corr + su;
            m[qi] = mn;
            u64 cp = pack2(corr, corr);
            fmul2(o2[qi][0], cp);
            fmul2(o2[qi][1], cp);
            p[qi] = pv;
        }

        // P @ V : lane owns dh dims [4*lane, 4*lane+4)
#pragma unroll 4
        for (int k = 0; k < 32; k++) {
            ulonglong2 v2 = *(const ulonglong2*)&Vs[(k << 5) + lane];
#pragma unroll
            for (int qi = 0; qi < 4; qi++) {
                float wq = __shfl_sync(0xffffffffu, p[qi], k);
                u64 wp = pack2(wq, wq);
                ffma2(o2[qi][0], wp, v2.x);
                ffma2(o2[qi][1], wp, v2.y);
            }
        }
    }

#pragma unroll
    for (int qi = 0; qi < 4; qi++) {
        float r = 1.f / l[qi];
        float2 a = unpack2(o2[qi][0]);
        float2 b = unpack2(o2[qi][1]);
        g_av4[(jbase + qi) * 32 + lane] =
            make_float4(a.x * r, a.y * r, b.x * r, b.y * r);
    }
}

// ---------------- residual + norm, accumulate into e ------------------------
__device__ __forceinline__ float block_sum(float v, float* red) {
#pragma unroll
    for (int off = 16; off; off >>= 1) v += __shfl_xor_sync(0xffffffffu, v, off);
    if ((threadIdx.x & 31) == 0) red[threadIdx.x >> 5] = v;
    __syncthreads();
    float s = ((red[0] + red[1]) + (red[2] + red[3])) +
              ((red[4] + red[5]) + (red[6] + red[7]));
    __syncthreads();
    return s;
}

__global__ void __launch_bounds__(256) k_norm(float* __restrict__ e) {
    __shared__ float red[8];
    const int r = blockIdx.x;
    const int tid = threadIdx.x;
    const float* dl = (const float*)g_delta4;
    float ev[4], o[4];
    float s1 = 0.f;
#pragma unroll
    for (int i = 0; i < 4; i++) {
        int idx = r * DEMB + tid + 256 * i;
        ev[i] = e[idx];
        o[i]  = ev[i] + dl[idx];
        s1 += o[i];
    }
    s1 = block_sum(s1, red);
    float inv_mean1 = (float)DEMB / s1;           // out /= mean(out)
    float s2 = 0.f;
#pragma unroll
    for (int i = 0; i < 4; i++) {
        o[i] *= inv_mean1;
        s2 += o[i];
    }
    s2 = block_sum(s2, red);
    float mu = s2 * (1.0f / DEMB);
    float sq = 0.f;
#pragma unroll
    for (int i = 0; i < 4; i++) {
        float d = o[i] - mu;
        sq += d * d;
    }
    sq = block_sum(sq, red);
    float inv_sd = rsqrtf(sq * (1.0f / (DEMB - 1)));  // ddof=1
#pragma unroll
    for (int i = 0; i < 4; i++) {
        int idx = r * DEMB + tid + 256 * i;
        e[idx] = ev[i] + (o[i] - mu) * inv_sd + mu;
    }
}

// ---------------- copy & final scale ----------------------------------------
__global__ void __launch_bounds__(256) k_copy(float4* __restrict__ dst,
                                              const float4* __restrict__ src) {
    int i = blockIdx.x * 256 + threadIdx.x;
    dst[i] = src[i];
}

__global__ void __launch_bounds__(256) k_scale(float4* __restrict__ e) {
    int i = blockIdx.x * 256 + threadIdx.x;
    float4 v = e[i];
    v.x *= 0.125f; v.y *= 0.125f; v.z *= 0.125f; v.w *= 0.125f;
    e[i] = v;
}

// ---------------- launch -----------------------------------------------------
extern "C" void kernel_launch(void* const* d_in, const int* in_sizes, int n_in,
                              void* d_out, int out_size) {
    const float* x   = (const float*)d_in[0];
    const float* Wq  = (const float*)d_in[1];
    const float* Wk  = (const float*)d_in[2];
    const float* Wvd = (const float*)d_in[3];
    const float* Wvu = (const float*)d_in[4];
    float* e = (float*)d_out;

    k_copy<<<NTOK * DEMB / 4 / 256, 256>>>((float4*)e, (const float4*)x);
    for (int h = 0; h < NH; h++) {
        k_gemm_qkv<<<dim3(1, 64, 3), 256>>>(e, Wq + (size_t)h * DH * DEMB,
                                            Wk + (size_t)h * DH * DEMB,
                                            Wvd + (size_t)h * DH * DEMB);
        k_attn<<<NTOK / 32, 256>>>();
        k_gemm_out<<<dim3(8, 32), 256>>>(Wvu + (size_t)h * DEMB * DH);
        k_norm<<<NTOK, 256>>>(e);
    }
    k_scale<<<NTOK * DEMB / 4 / 256, 256>>>((float4*)e);
}

// round 13
// speedup vs baseline: 1.6671x; 1.6671x over previous
#include <cuda_runtime.h>
#include <cuda_fp16.h>
#include <mma.h>
#include <float.h>
#include <stdint.h>

using namespace nvcuda;

#define NTOK 4096
#define DEMB 1024
#define NH   8
#define DH   128
#define CWW  256
#define QK_SCALE 0.08838834764831845f  // 1/sqrt(128)

// ---------------- scratch (static device memory; no allocations) ------------
__device__ float4 g_q4[NTOK * DH / 4];
__device__ float4 g_k4[NTOK * DH / 4];
__device__ float4 g_v4[NTOK * DH / 4];
__device__ float4 g_av4[NTOK * DH / 4];
__device__ float4 g_delta4[NTOK * DEMB / 4];

// ---------------- split-fp16 wmma GEMM (fp32 in, fp32 out) -------------------
// C[64 rows, 128 cols] per CTA: C[n][m] = sum_k A[n][k]*B[m][k].
// A/B read as fp32 from gmem; hi/lo fp16 split done in registers at staging.
// Near-fp32: Ah*Bh + Ah*Bl + Al*Bh with fp32 accumulators (err ~2^-22).
// 8 warps as 2(m) x 4(n); each warp 32x32 = 2x2 wmma 16x16x16 tiles.
#define SST 48   // smem row stride in halves (96B; ldm mult of 8, 32B aligned)

template <int K>
__device__ __forceinline__ void wmma_gemm_f32(
    const float* __restrict__ Ag,   // pre-offset: + n0*K
    const float* __restrict__ Bg,   // pre-offset: + m0*K (128 rows)
    float* __restrict__ C, int CS)  // pre-offset: + n0*CS + m0
{
    __shared__ __align__(32) __half sm[18432];  // 36 KB static
    __half* const sAh = sm;                     // 64 x 48
    __half* const sAl = sm + 3072;              // 64 x 48
    __half* const sBh = sm + 6144;              // 128 x 48
    __half* const sBl = sm + 12288;             // 128 x 48

    const int tid = threadIdx.x;
    const int wid = tid >> 5;
    const int wm  = (wid & 1) * 32;   // warp row base in 64
    const int wn  = (wid >> 1) * 32;  // warp col base in 128

    wmma::fragment<wmma::accumulator, 16, 16, 16, float> acc[2][2];
#pragma unroll
    for (int mt = 0; mt < 2; mt++)
#pragma unroll
        for (int nt = 0; nt < 2; nt++) wmma::fill_fragment(acc[mt][nt], 0.0f);

#pragma unroll 1
    for (int kc = 0; kc < K; kc += 32) {
        // stage A: 64x32 fp32 -> hi/lo halves. 8 floats per thread.
        {
            int r  = tid >> 2;            // 0..63
            int kq = (tid & 3) * 8;       // 0,8,16,24
            const float* src = Ag + (size_t)r * K + kc + kq;
            float4 f0 = *(const float4*)src;
            float4 f1 = *(const float4*)(src + 4);
            float fa[8] = {f0.x, f0.y, f0.z, f0.w, f1.x, f1.y, f1.z, f1.w};
            __half hh[8], ll[8];
#pragma unroll
            for (int q = 0; q < 8; q++) {
                hh[q] = __float2half_rn(fa[q]);
                ll[q] = __float2half_rn(fa[q] - __half2float(hh[q]));
            }
            *(uint4*)(sAh + r * SST + kq) = *(uint4*)hh;
            *(uint4*)(sAl + r * SST + kq) = *(uint4*)ll;
        }
        // stage B: 128x32 fp32 -> hi/lo halves. 16 floats per thread.
#pragma unroll
        for (int v = 0; v < 2; v++) {
            int idx = v * 256 + tid;      // 0..511
            int r   = idx >> 2;           // 0..127
            int kq  = (idx & 3) * 8;
            const float* src = Bg + (size_t)r * K + kc + kq;
            float4 f0 = *(const float4*)src;
            float4 f1 = *(const float4*)(src + 4);
            float fa[8] = {f0.x, f0.y, f0.z, f0.w, f1.x, f1.y, f1.z, f1.w};
            __half hh[8], ll[8];
#pragma unroll
            for (int q = 0; q < 8; q++) {
                hh[q] = __float2half_rn(fa[q]);
                ll[q] = __float2half_rn(fa[q] - __half2float(hh[q]));
            }
            *(uint4*)(sBh + r * SST + kq) = *(uint4*)hh;
            *(uint4*)(sBl + r * SST + kq) = *(uint4*)ll;
        }
        __syncthreads();

#pragma unroll
        for (int ks = 0; ks < 2; ks++) {
            wmma::fragment<wmma::matrix_a, 16, 16, 16, __half, wmma::row_major> ah[2], al[2];
            wmma::fragment<wmma::matrix_b, 16, 16, 16, __half, wmma::col_major> bh[2], bl[2];
#pragma unroll
            for (int mt = 0; mt < 2; mt++) {
                wmma::load_matrix_sync(ah[mt], sAh + (wm + mt * 16) * SST + ks * 16, SST);
                wmma::load_matrix_sync(al[mt], sAl + (wm + mt * 16) * SST + ks * 16, SST);
            }
#pragma unroll
            for (int nt = 0; nt < 2; nt++) {
                wmma::load_matrix_sync(bh[nt], sBh + (wn + nt * 16) * SST + ks * 16, SST);
                wmma::load_matrix_sync(bl[nt], sBl + (wn + nt * 16) * SST + ks * 16, SST);
            }
#pragma unroll
            for (int mt = 0; mt < 2; mt++)
#pragma unroll
                for (int nt = 0; nt < 2; nt++) {
                    wmma::mma_sync(acc[mt][nt], ah[mt], bh[nt], acc[mt][nt]);
                    wmma::mma_sync(acc[mt][nt], ah[mt], bl[nt], acc[mt][nt]);
                    wmma::mma_sync(acc[mt][nt], al[mt], bh[nt], acc[mt][nt]);
                }
        }
        __syncthreads();
    }

#pragma unroll
    for (int mt = 0; mt < 2; mt++)
#pragma unroll
        for (int nt = 0; nt < 2; nt++)
            wmma::store_matrix_sync(C + (size_t)(wm + mt * 16) * CS + wn + nt * 16,
                                    acc[mt][nt], CS, wmma::mem_row_major);
}

// QKV: grid (64, 3). q/k/vd = e @ W[h]^T, K=1024, C stride 128.
__global__ void __launch_bounds__(256) k_gemm_qkv(const float* __restrict__ e,
                                                  const float* __restrict__ Wq,
                                                  const float* __restrict__ Wk,
                                                  const float* __restrict__ Wvd) {
    const int n0 = blockIdx.x * 64;
    const int sel = blockIdx.y;
    const float* B = (sel == 0) ? Wq : (sel == 1 ? Wk : Wvd);
    float* C = (sel == 0) ? (float*)g_q4 : (sel == 1 ? (float*)g_k4 : (float*)g_v4);
    wmma_gemm_f32<DEMB>(e + (size_t)n0 * DEMB, B, C + (size_t)n0 * DH, DH);
}

// out projection: grid (64, 8). delta = av @ Wvu[h]^T, K=128, C stride 1024.
__global__ void __launch_bounds__(256) k_gemm_out(const float* __restrict__ Wvu) {
    const int n0 = blockIdx.x * 64;
    const int m0 = blockIdx.y * 128;
    wmma_gemm_f32<DH>((const float*)g_av4 + (size_t)n0 * DH,
                      Wvu + (size_t)m0 * DH,
                      (float*)g_delta4 + (size_t)n0 * DEMB + m0, DEMB);
}

// ---------------- banded attention (online softmax, fp32 SIMT; R3-proven) ---
__global__ void __launch_bounds__(256) k_attn() {
    __shared__ float4 Qs[32 * 32];  // [q][d4]
    __shared__ float4 Kt[32 * 32];  // [d4][key ^ d4]
    __shared__ float4 Vs[32 * 32];  // [key][d4]
    const int tid  = threadIdx.x;
    const int lane = tid & 31;
    const int w    = tid >> 5;
    const int q0   = blockIdx.x * 32;

#pragma unroll
    for (int i = 0; i < 4; i++)
        Qs[tid + 256 * i] = g_q4[q0 * 32 + tid + 256 * i];

    float m[4], l[4];
    float4 o[4];
#pragma unroll
    for (int qi = 0; qi < 4; qi++) {
        m[qi] = -FLT_MAX;
        l[qi] = 0.f;
        o[qi] = make_float4(0.f, 0.f, 0.f, 0.f);
    }
    const int jbase = q0 + 4 * w;
    const int lo = (q0 >= CWW) ? (q0 - CWW) : 0;
    const int hi = min(q0 + 31 + CWW, NTOK);

    for (int kc = lo; kc < hi; kc += 32) {
        __syncthreads();
#pragma unroll
        for (int i = 0; i < 4; i++) {
            int idx = tid + 256 * i;
            int key = idx >> 5;
            int d4  = idx & 31;
            int kg  = kc + key;
            float4 kv = make_float4(0.f, 0.f, 0.f, 0.f);
            float4 vv = make_float4(0.f, 0.f, 0.f, 0.f);
            if (kg < NTOK) {
                kv = g_k4[kg * 32 + d4];
                vv = g_v4[kg * 32 + d4];
            }
            Kt[(d4 << 5) + (key ^ d4)] = kv;
            Vs[(key << 5) + d4] = vv;
        }
        __syncthreads();

        float s[4] = {0.f, 0.f, 0.f, 0.f};
#pragma unroll 8
        for (int d4 = 0; d4 < 32; d4++) {
            float4 kv = Kt[(d4 << 5) + (lane ^ d4)];
#pragma unroll
            for (int qi = 0; qi < 4; qi++) {
                float4 qv = Qs[(4 * w + qi) * 32 + d4];
                s[qi] += qv.x * kv.x + qv.y * kv.y + qv.z * kv.z + qv.w * kv.w;
            }
        }

        const int kg = kc + lane;
        float p[4];
#pragma unroll
        for (int qi = 0; qi < 4; qi++) {
            int j = jbase + qi;
            float sv = s[qi] * QK_SCALE;
            bool ok = (kg >= j - CWW) && (kg < j + CWW) && (kg < NTOK);
            sv = ok ? sv : -FLT_MAX;
            float c = sv;
#pragma unroll
            for (int off = 16; off; off >>= 1)
                c = fmaxf(c, __shfl_xor_sync(0xffffffffu, c, off));
            float mn   = fmaxf(m[qi], c);
            float corr = __expf(m[qi] - mn);
            float pv   = __expf(sv - mn);
            float su = pv;
#pragma unroll
            for (int off = 16; off; off >>= 1)
                su += __shfl_xor_sync(0xffffffffu, su, off);
            l[qi] = l[qi] * corr + su;
            m[qi] = mn;
            o[qi].x *= corr; o[qi].y *= corr; o[qi].z *= corr; o[qi].w *= corr;
            p[qi] = pv;
        }

#pragma unroll 4
        for (int k = 0; k < 32; k++) {
            float4 v = Vs[(k << 5) + lane];
#pragma unroll
            for (int qi = 0; qi < 4; qi++) {
                float wq = __shfl_sync(0xffffffffu, p[qi], k);
                o[qi].x += wq * v.x;
                o[qi].y += wq * v.y;
                o[qi].z += wq * v.z;
                o[qi].w += wq * v.w;
            }
        }
    }

#pragma unroll
    for (int qi = 0; qi < 4; qi++) {
        float r = 1.f / l[qi];
        g_av4[(jbase + qi) * 32 + lane] =
            make_float4(o[qi].x * r, o[qi].y * r, o[qi].z * r, o[qi].w * r);
    }
}

// ---------------- residual + norm (R3-proven) --------------------------------
__device__ __forceinline__ float block_sum(float v, float* red) {
#pragma unroll
    for (int off = 16; off; off >>= 1) v += __shfl_xor_sync(0xffffffffu, v, off);
    if ((threadIdx.x & 31) == 0) red[threadIdx.x >> 5] = v;
    __syncthreads();
    float s = ((red[0] + red[1]) + (red[2] + red[3])) +
              ((red[4] + red[5]) + (red[6] + red[7]));
    __syncthreads();
    return s;
}

__global__ void __launch_bounds__(256) k_norm(float* __restrict__ e) {
    __shared__ float red[8];
    const int r = blockIdx.x;
    const int tid = threadIdx.x;
    const float* dl = (const float*)g_delta4;
    float ev[4], o[4];
    float s1 = 0.f;
#pragma unroll
    for (int i = 0; i < 4; i++) {
        int idx = r * DEMB + tid + 256 * i;
        ev[i] = e[idx];
        o[i]  = ev[i] + dl[idx];
        s1 += o[i];
    }
    s1 = block_sum(s1, red);
    float inv_mean1 = (float)DEMB / s1;           // out /= mean(out)
    float s2 = 0.f;
#pragma unroll
    for (int i = 0; i < 4; i++) {
        o[i] *= inv_mean1;
        s2 += o[i];
    }
    s2 = block_sum(s2, red);
    float mu = s2 * (1.0f / DEMB);
    float sq = 0.f;
#pragma unroll
    for (int i = 0; i < 4; i++) {
        float d = o[i] - mu;
        sq += d * d;
    }
    sq = block_sum(sq, red);
    float inv_sd = rsqrtf(sq * (1.0f / (DEMB - 1)));  // ddof=1
#pragma unroll
    for (int i = 0; i < 4; i++) {
        int idx = r * DEMB + tid + 256 * i;
        e[idx] = ev[i] + (o[i] - mu) * inv_sd + mu;
    }
}

// ---------------- copy & final scale -----------------------------------------
__global__ void __launch_bounds__(256) k_copy(float4* __restrict__ dst,
                                              const float4* __restrict__ src) {
    int i = blockIdx.x * 256 + threadIdx.x;
    dst[i] = src[i];
}

__global__ void __launch_bounds__(256) k_scale(float4* __restrict__ e) {
    int i = blockIdx.x * 256 + threadIdx.x;
    float4 v = e[i];
    v.x *= 0.125f; v.y *= 0.125f; v.z *= 0.125f; v.w *= 0.125f;
    e[i] = v;
}

// ---------------- launch -----------------------------------------------------
extern "C" void kernel_launch(void* const* d_in, const int* in_sizes, int n_in,
                              void* d_out, int out_size) {
    const float* x   = (const float*)d_in[0];
    const float* Wq  = (const float*)d_in[1];
    const float* Wk  = (const float*)d_in[2];
    const float* Wvd = (const float*)d_in[3];
    const float* Wvu = (const float*)d_in[4];
    float* e = (float*)d_out;

    k_copy<<<NTOK * DEMB / 4 / 256, 256>>>((float4*)e, (const float4*)x);
    for (int h = 0; h < NH; h++) {
        k_gemm_qkv<<<dim3(64, 3), 256>>>(e, Wq + (size_t)h * DH * DEMB,
                                         Wk + (size_t)h * DH * DEMB,
                                         Wvd + (size_t)h * DH * DEMB);
        k_attn<<<NTOK / 32, 256>>>();
        k_gemm_out<<<dim3(64, 8), 256>>>(Wvu + (size_t)h * DEMB * DH);
        k_norm<<<NTOK, 256>>>(e);
    }
    k_scale<<<NTOK * DEMB / 4 / 256, 256>>>((float4*)e);
}